// round 7
// baseline (speedup 1.0000x reference)
#include <cuda_runtime.h>
#include <cuda_fp16.h>

#define NN 100000
#define EE 1600000
#define GG 1024

typedef unsigned long long ull;

// -------------------- device scratch --------------------
__device__ float g_A[(size_t)NN * 64];     // layer-1 aggregation output (fp32)
__device__ float g_B[(size_t)NN * 64];     // raw layer outputs (fp32)
__device__ uint4 g_H[(size_t)NN * 8];      // activated features fp16 (64 halves/node)
__device__ float g_xpad[(size_t)NN * 16];
__device__ int   g_off[NN + 1];
__device__ int   g_cur[NN];
__device__ int   g_bsum[128];
__device__ int2  g_epack[EE];              // (src, weight-bits) grouped by dst
__device__ int   g_goff[GG + 1];
__device__ float g_stats[256];             // [0:128) layer0, [128:256) layer1

__device__ __forceinline__ void fma2(ull& d, ull a, ull b) {
    asm("fma.rn.f32x2 %0, %1, %2, %0;" : "+l"(d) : "l"(a), "l"(b));
}
__device__ __forceinline__ float2 unpack2(ull v) {
    float2 r; asm("mov.b64 {%0,%1}, %2;" : "=f"(r.x), "=f"(r.y) : "l"(v)); return r;
}
__device__ __forceinline__ ull pack2(float lo, float hi) {
    ull r; asm("mov.b64 %0, {%1,%2};" : "=l"(r) : "f"(lo), "f"(hi)); return r;
}

// -------------------- fused prep: hist + xpad + graph bounds --------------------
__global__ void prep(const float* __restrict__ x, float* __restrict__ xp,
                     const int* __restrict__ dst, int* __restrict__ off,
                     const int* __restrict__ batch, int* __restrict__ goff) {
    int i = blockIdx.x * blockDim.x + threadIdx.x;
    if (i < EE) atomicAdd(&off[dst[i] + 1], 1);
    if (i < NN * 16) { int n = i >> 4, c = i & 15; xp[i] = (c < 9) ? x[n * 9 + c] : 0.f; }
    if (i < NN) {
        int bi = batch[i];
        if (i == 0) { for (int g = 0; g <= bi; g++) goff[g] = 0; }
        else { int bp = batch[i - 1]; for (int g = bp + 1; g <= bi; g++) goff[g] = i; }
        if (i == NN - 1) { for (int g = bi + 1; g <= GG; g++) goff[g] = NN; }
    }
}

// -------------------- scan --------------------
__global__ void scan1(int* __restrict__ off, int* __restrict__ bsum) {
    __shared__ int ws[32];
    int g = blockIdx.x * 1024 + threadIdx.x;
    int v = (g <= NN) ? off[g] : 0;
    int lane = threadIdx.x & 31;
#pragma unroll
    for (int d = 1; d < 32; d <<= 1) { int t = __shfl_up_sync(~0u, v, d); if (lane >= d) v += t; }
    if (lane == 31) ws[threadIdx.x >> 5] = v;
    __syncthreads();
    if (threadIdx.x < 32) {
        int t = ws[threadIdx.x];
#pragma unroll
        for (int d = 1; d < 32; d <<= 1) { int u = __shfl_up_sync(~0u, t, d); if (threadIdx.x >= d) t += u; }
        ws[threadIdx.x] = t;
    }
    __syncthreads();
    if (threadIdx.x >= 32) v += ws[(threadIdx.x >> 5) - 1];
    if (g <= NN) off[g] = v;
    if (threadIdx.x == 1023) bsum[blockIdx.x] = v;
}

__global__ void scan3f(int* __restrict__ off, const int* __restrict__ bsum, int* __restrict__ cur) {
    __shared__ int red[32];
    __shared__ int sadd;
    int t = threadIdx.x;
    int v = (t < blockIdx.x) ? bsum[t] : 0;
#pragma unroll
    for (int d = 16; d; d >>= 1) v += __shfl_down_sync(~0u, v, d);
    if ((t & 31) == 0) red[t >> 5] = v;
    __syncthreads();
    if (t == 0) { int r = 0; for (int w = 0; w < 32; w++) r += red[w]; sadd = r; }
    __syncthreads();
    int g = blockIdx.x * 1024 + t;
    if (g > NN) return;
    int val = off[g] + sadd;
    off[g] = val;
    if (g < NN) cur[g] = val;
}

__global__ void place_kernel(const int* __restrict__ src, const int* __restrict__ dst,
                             const float* __restrict__ ew, int* __restrict__ cur,
                             int2* __restrict__ epack) {
    int e = blockIdx.x * blockDim.x + threadIdx.x;
    if (e >= EE) return;
    int p = atomicAdd(&cur[dst[e]], 1);
    epack[p] = make_int2(src[e], __float_as_int(ew[e]));
}

// -------------------- layer-0 CSR aggregation (fp32, 16-wide padded) ------------
__global__ void __launch_bounds__(256) agg_csr4(
    const float* __restrict__ h, const int* __restrict__ rowptr,
    const int2* __restrict__ epack, float* __restrict__ agg, float* __restrict__ stats) {
    if (blockIdx.x == 0) stats[threadIdx.x] = 0.f;   // zero both stats banks
    int node = blockIdx.x * 64 + (threadIdx.x >> 2);
    int lane = threadIdx.x & 3;
    if (node >= NN) return;
    int beg = rowptr[node], end = rowptr[node + 1];
    float4 acc = make_float4(0.f, 0.f, 0.f, 0.f);
    for (int i = beg; i < end; ++i) {
        int2 ep = epack[i];
        float w = __int_as_float(ep.y);
        float4 v = ((const float4*)h)[(size_t)ep.x * 4 + lane];
        acc.x = fmaf(v.x, w, acc.x);
        acc.y = fmaf(v.y, w, acc.y);
        acc.z = fmaf(v.z, w, acc.z);
        acc.w = fmaf(v.w, w, acc.w);
    }
    ((float4*)agg)[(size_t)node * 4 + lane] = acc;
}

// -------------------- layer-1 CSR aggregation, fp16 rows --------------------
__device__ __forceinline__ void accum8(float* acc, uint4 r, float w) {
    __half2* hp = (__half2*)&r;
#pragma unroll
    for (int j = 0; j < 4; j++) {
        float2 f = __half22float2(hp[j]);
        acc[2 * j]     = fmaf(f.x, w, acc[2 * j]);
        acc[2 * j + 1] = fmaf(f.y, w, acc[2 * j + 1]);
    }
}

__global__ void __launch_bounds__(256) agg_csr_h(
    const uint4* __restrict__ h, const int* __restrict__ rowptr,
    const int2* __restrict__ epack, float* __restrict__ agg) {
    int node = blockIdx.x * 32 + (threadIdx.x >> 3);
    int lane = threadIdx.x & 7;
    if (node >= NN) return;
    int beg = rowptr[node], end = rowptr[node + 1];
    float acc[8];
#pragma unroll
    for (int j = 0; j < 8; j++) acc[j] = 0.f;
    int i = beg;
    for (; i + 1 < end; i += 2) {
        int2 e0 = epack[i], e1 = epack[i + 1];
        uint4 r0 = h[(size_t)e0.x * 8 + lane];
        uint4 r1 = h[(size_t)e1.x * 8 + lane];
        accum8(acc, r0, __int_as_float(e0.y));
        accum8(acc, r1, __int_as_float(e1.y));
    }
    if (i < end) {
        int2 e0 = epack[i];
        uint4 r0 = h[(size_t)e0.x * 8 + lane];
        accum8(acc, r0, __int_as_float(e0.y));
    }
    float* dstp = &agg[(size_t)node * 64 + lane * 8];
    *(float4*)dstp       = make_float4(acc[0], acc[1], acc[2], acc[3]);
    *(float4*)(dstp + 4) = make_float4(acc[4], acc[5], acc[6], acc[7]);
}

// -------------------- layer-0 node update (K=9, scalar) --------------------
__global__ void __launch_bounds__(128) node_update9(
    const float* __restrict__ Ag, const float* __restrict__ Xin,
    const float* __restrict__ Wrel, const float* __restrict__ Wroot,
    const float* __restrict__ bias, float* __restrict__ Out, float* stats) {
    constexpr int K = 9, PAD = 17, C4 = 4;
    extern __shared__ float sm[];
    float* sA   = sm;
    float* sX   = sA + 64 * PAD;
    float* sWr  = sX + 64 * PAD;
    float* sWo  = sWr + K * 64;
    float* sSum = sWo + K * 64;
    float* sSq  = sSum + 64;

    const int tid = threadIdx.x;
    const int base = blockIdx.x * 64;

    for (int i = tid; i < K * 16; i += 128) {
        ((float4*)sWr)[i] = ((const float4*)Wrel)[i];
        ((float4*)sWo)[i] = ((const float4*)Wroot)[i];
    }
    for (int i = tid; i < 64 * C4; i += 128) {
        int r = i / C4, c = i - r * C4;
        int n = base + r;
        float4 va = make_float4(0.f, 0.f, 0.f, 0.f), vx = va;
        if (n < NN) {
            va = *(const float4*)&Ag[(size_t)n * 16 + c * 4];
            vx = *(const float4*)&Xin[(size_t)n * 16 + c * 4];
        }
        int o = r * PAD + c * 4;
        sA[o] = va.x; sA[o + 1] = va.y; sA[o + 2] = va.z; sA[o + 3] = va.w;
        sX[o] = vx.x; sX[o + 1] = vx.y; sX[o + 2] = vx.z; sX[o + 3] = vx.w;
    }
    if (tid < 64) { sSum[tid] = 0.f; sSq[tid] = 0.f; }
    __syncthreads();

    const int fg = (tid & 7) * 8;
    const int ng = (tid >> 3) * 4;

    float acc[4][8];
#pragma unroll
    for (int i = 0; i < 4; i++)
#pragma unroll
        for (int j = 0; j < 8; j++) acc[i][j] = 0.f;

#pragma unroll
    for (int k = 0; k < K; ++k) {
        float a[4], xv[4];
#pragma unroll
        for (int i = 0; i < 4; i++) {
            a[i]  = sA[(ng + i) * PAD + k];
            xv[i] = sX[(ng + i) * PAD + k];
        }
        float wr[8], wo[8];
        *(float4*)&wr[0] = *(const float4*)&sWr[k * 64 + fg];
        *(float4*)&wr[4] = *(const float4*)&sWr[k * 64 + fg + 4];
        *(float4*)&wo[0] = *(const float4*)&sWo[k * 64 + fg];
        *(float4*)&wo[4] = *(const float4*)&sWo[k * 64 + fg + 4];
#pragma unroll
        for (int i = 0; i < 4; i++)
#pragma unroll
            for (int j = 0; j < 8; j++)
                acc[i][j] = fmaf(xv[i], wo[j], fmaf(a[i], wr[j], acc[i][j]));
    }

    float bz[8];
    *(float4*)&bz[0] = *(const float4*)&bias[fg];
    *(float4*)&bz[4] = *(const float4*)&bias[fg + 4];

    float s[8], q[8];
#pragma unroll
    for (int j = 0; j < 8; j++) { s[j] = 0.f; q[j] = 0.f; }

#pragma unroll
    for (int i = 0; i < 4; i++) {
        int n = base + ng + i;
        if (n < NN) {
            float o[8];
#pragma unroll
            for (int j = 0; j < 8; j++) o[j] = acc[i][j] + bz[j];
            *(float4*)&Out[(size_t)n * 64 + fg]     = make_float4(o[0], o[1], o[2], o[3]);
            *(float4*)&Out[(size_t)n * 64 + fg + 4] = make_float4(o[4], o[5], o[6], o[7]);
#pragma unroll
            for (int j = 0; j < 8; j++) { s[j] += o[j]; q[j] += o[j] * o[j]; }
        }
    }
#pragma unroll
    for (int j = 0; j < 8; j++) {
        atomicAdd(&sSum[fg + j], s[j]);
        atomicAdd(&sSq[fg + j], q[j]);
    }
    __syncthreads();
    if (tid < 64) {
        atomicAdd(&stats[tid], sSum[tid]);
        atomicAdd(&stats[64 + tid], sSq[tid]);
    }
}

// -------------------- f32x2 node update (K=64), fp16 Xin --------------------
__global__ void __launch_bounds__(128) node_update64(
    const float* __restrict__ Ag, const uint4* __restrict__ Xh,
    const float* __restrict__ Wrel, const float* __restrict__ Wroot,
    const float* __restrict__ bias, float* __restrict__ Out, float* stats) {
    constexpr int PAD = 66;
    extern __shared__ float sm[];
    float* sA   = sm;
    float* sX   = sA + 64 * PAD;
    ull*   sWr  = (ull*)(sX + 64 * PAD);
    ull*   sWo  = sWr + 32 * 64;
    float* sSum = (float*)(sWo + 32 * 64);
    float* sSq  = sSum + 64;

    const int tid = threadIdx.x;
    const int base = blockIdx.x * 64;

    for (int idx = tid; idx < 32 * 16; idx += 128) {
        int k2 = idx >> 4, c4 = idx & 15;
        float4 r0 = ((const float4*)Wrel)[(2 * k2) * 16 + c4];
        float4 r1 = ((const float4*)Wrel)[(2 * k2 + 1) * 16 + c4];
        ull* p = &sWr[k2 * 64 + c4 * 4];
        p[0] = pack2(r0.x, r1.x); p[1] = pack2(r0.y, r1.y);
        p[2] = pack2(r0.z, r1.z); p[3] = pack2(r0.w, r1.w);
        r0 = ((const float4*)Wroot)[(2 * k2) * 16 + c4];
        r1 = ((const float4*)Wroot)[(2 * k2 + 1) * 16 + c4];
        p = &sWo[k2 * 64 + c4 * 4];
        p[0] = pack2(r0.x, r1.x); p[1] = pack2(r0.y, r1.y);
        p[2] = pack2(r0.z, r1.z); p[3] = pack2(r0.w, r1.w);
    }
    for (int i = tid; i < 64 * 16; i += 128) {
        int r = i >> 4, c = i & 15;
        int n = base + r;
        float4 va = make_float4(0.f, 0.f, 0.f, 0.f);
        if (n < NN) va = *(const float4*)&Ag[(size_t)n * 64 + c * 4];
        int o = r * PAD + c * 4;
        sA[o] = va.x; sA[o + 1] = va.y; sA[o + 2] = va.z; sA[o + 3] = va.w;
    }
    for (int i = tid; i < 64 * 8; i += 128) {
        int r = i >> 3, c = i & 7;
        int n = base + r;
        uint4 v = make_uint4(0u, 0u, 0u, 0u);
        if (n < NN) v = Xh[(size_t)n * 8 + c];
        __half2* hp = (__half2*)&v;
        float* o = &sX[r * PAD + c * 8];
#pragma unroll
        for (int j = 0; j < 4; j++) {
            float2 f = __half22float2(hp[j]);
            o[2 * j] = f.x; o[2 * j + 1] = f.y;
        }
    }
    if (tid < 64) { sSum[tid] = 0.f; sSq[tid] = 0.f; }
    __syncthreads();

    const int f0 = (tid & 7) * 2;
    const int ng = (tid >> 3) * 4;

    ull acc2[4][8];
#pragma unroll
    for (int i = 0; i < 4; i++)
#pragma unroll
        for (int j = 0; j < 8; j++) acc2[i][j] = 0ull;

#pragma unroll 2
    for (int k2 = 0; k2 < 32; ++k2) {
        ull av[4], xv[4];
#pragma unroll
        for (int i = 0; i < 4; i++) {
            av[i] = *(const ull*)&sA[(ng + i) * PAD + 2 * k2];
            xv[i] = *(const ull*)&sX[(ng + i) * PAD + 2 * k2];
        }
#pragma unroll
        for (int c = 0; c < 4; c++) {
            ulonglong2 wr = *(const ulonglong2*)&sWr[k2 * 64 + f0 + 16 * c];
            ulonglong2 wo = *(const ulonglong2*)&sWo[k2 * 64 + f0 + 16 * c];
#pragma unroll
            for (int i = 0; i < 4; i++) {
                fma2(acc2[i][2 * c],     av[i], wr.x);
                fma2(acc2[i][2 * c + 1], av[i], wr.y);
                fma2(acc2[i][2 * c],     xv[i], wo.x);
                fma2(acc2[i][2 * c + 1], xv[i], wo.y);
            }
        }
    }

    float bz[8];
#pragma unroll
    for (int c = 0; c < 4; c++) {
        float2 b2 = *(const float2*)&bias[f0 + 16 * c];
        bz[2 * c] = b2.x; bz[2 * c + 1] = b2.y;
    }

    float s[8], q[8];
#pragma unroll
    for (int j = 0; j < 8; j++) { s[j] = 0.f; q[j] = 0.f; }

#pragma unroll
    for (int i = 0; i < 4; i++) {
        int n = base + ng + i;
        if (n < NN) {
#pragma unroll
            for (int c = 0; c < 4; c++) {
                float2 e0 = unpack2(acc2[i][2 * c]);
                float2 e1 = unpack2(acc2[i][2 * c + 1]);
                float o0 = e0.x + e0.y + bz[2 * c];
                float o1 = e1.x + e1.y + bz[2 * c + 1];
                *(float2*)&Out[(size_t)n * 64 + f0 + 16 * c] = make_float2(o0, o1);
                s[2 * c] += o0; q[2 * c] += o0 * o0;
                s[2 * c + 1] += o1; q[2 * c + 1] += o1 * o1;
            }
        }
    }
#pragma unroll
    for (int c = 0; c < 4; c++) {
        atomicAdd(&sSum[f0 + 16 * c],     s[2 * c]);
        atomicAdd(&sSum[f0 + 16 * c + 1], s[2 * c + 1]);
        atomicAdd(&sSq[f0 + 16 * c],      q[2 * c]);
        atomicAdd(&sSq[f0 + 16 * c + 1],  q[2 * c + 1]);
    }
    __syncthreads();
    if (tid < 64) {
        atomicAdd(&stats[tid], sSum[tid]);
        atomicAdd(&stats[64 + tid], sSq[tid]);
    }
}

// -------------------- BN finalize + apply + ReLU + fp16 convert (fused) --------
__global__ void __launch_bounds__(256) bn_act_h(
    const float* __restrict__ in, const float* __restrict__ stats,
    const float* __restrict__ g, const float* __restrict__ be,
    uint4* __restrict__ outh) {
    __shared__ float sc[64], sh[64];
    if (threadIdx.x < 64) {
        int f = threadIdx.x;
        const float inv = 1.f / (float)NN;
        float m = stats[f] * inv;
        float var = stats[64 + f] * inv - m * m;
        float s = g[f] * rsqrtf(var + 1e-5f);
        sc[f] = s;
        sh[f] = fmaf(-m, s, be[f]);
    }
    __syncthreads();
    int i = blockIdx.x * blockDim.x + threadIdx.x;
    if (i >= NN * 8) return;
    int c8 = (i & 7) * 8;
    float4 a = ((const float4*)in)[2 * i];
    float4 b = ((const float4*)in)[2 * i + 1];
    a.x = fmaxf(fmaf(a.x, sc[c8 + 0], sh[c8 + 0]), 0.f);
    a.y = fmaxf(fmaf(a.y, sc[c8 + 1], sh[c8 + 1]), 0.f);
    a.z = fmaxf(fmaf(a.z, sc[c8 + 2], sh[c8 + 2]), 0.f);
    a.w = fmaxf(fmaf(a.w, sc[c8 + 3], sh[c8 + 3]), 0.f);
    b.x = fmaxf(fmaf(b.x, sc[c8 + 4], sh[c8 + 4]), 0.f);
    b.y = fmaxf(fmaf(b.y, sc[c8 + 5], sh[c8 + 5]), 0.f);
    b.z = fmaxf(fmaf(b.z, sc[c8 + 6], sh[c8 + 6]), 0.f);
    b.w = fmaxf(fmaf(b.w, sc[c8 + 7], sh[c8 + 7]), 0.f);
    __half2 h0 = __floats2half2_rn(a.x, a.y);
    __half2 h1 = __floats2half2_rn(a.z, a.w);
    __half2 h2 = __floats2half2_rn(b.x, b.y);
    __half2 h3 = __floats2half2_rn(b.z, b.w);
    uint4 o;
    o.x = *(unsigned*)&h0; o.y = *(unsigned*)&h1;
    o.z = *(unsigned*)&h2; o.w = *(unsigned*)&h3;
    outh[i] = o;
}

// -------------------- layer-2 fully fused: per-graph edge/node segment sums +
// pooled GEMM + MLP head. Edges are dst-grouped and dst is batch-sorted, so the
// edge range of graph g is [off[goff[g]], off[goff[g+1]]). ------------------------
__global__ void __launch_bounds__(256) pool2_head(
    const uint4* __restrict__ Xh, const int* __restrict__ off,
    const int2* __restrict__ epack, const int* __restrict__ goff,
    const float* __restrict__ W2rel, const float* __restrict__ W2root,
    const float* __restrict__ b2,
    const float* __restrict__ Wl1, const float* __restrict__ bl1,
    const float* __restrict__ Wl2, const float* __restrict__ bl2,
    float* __restrict__ out) {
    __shared__ float sAg[4][64], sXp[4][64];
    __shared__ float sPool[64], sz[64];
    int g = blockIdx.x, t = threadIdx.x;
    int lane = t >> 6;        // 0..3
    int f = t & 63;
    int nb = goff[g], ne = goff[g + 1];
    int eb = off[nb], ee = off[ne];
    const __half* xh = (const __half*)Xh;

    // edge segment: sa = sum_e w_e * h_src[f]
    float sa = 0.f;
    int e = eb + lane;
    for (; e + 12 < ee; e += 16) {
        int2 p0 = epack[e], p1 = epack[e + 4], p2 = epack[e + 8], p3 = epack[e + 12];
        float v0 = __half2float(xh[(size_t)p0.x * 64 + f]);
        float v1 = __half2float(xh[(size_t)p1.x * 64 + f]);
        float v2 = __half2float(xh[(size_t)p2.x * 64 + f]);
        float v3 = __half2float(xh[(size_t)p3.x * 64 + f]);
        sa = fmaf(v0, __int_as_float(p0.y), sa);
        sa = fmaf(v1, __int_as_float(p1.y), sa);
        sa = fmaf(v2, __int_as_float(p2.y), sa);
        sa = fmaf(v3, __int_as_float(p3.y), sa);
    }
    for (; e < ee; e += 4) {
        int2 p0 = epack[e];
        sa = fmaf(__half2float(xh[(size_t)p0.x * 64 + f]), __int_as_float(p0.y), sa);
    }
    // node segment: sx = sum_n h_n[f]
    float sx = 0.f;
    int n = nb + lane;
    for (; n + 12 < ne; n += 16) {
        sx += __half2float(xh[(size_t)n * 64 + f])
            + __half2float(xh[(size_t)(n + 4) * 64 + f])
            + __half2float(xh[(size_t)(n + 8) * 64 + f])
            + __half2float(xh[(size_t)(n + 12) * 64 + f]);
    }
    for (; n < ne; n += 4) sx += __half2float(xh[(size_t)n * 64 + f]);

    sAg[lane][f] = sa;
    sXp[lane][f] = sx;
    __syncthreads();

    if (t < 64) {
        float cnt = (float)(ne - nb);
        // pooled layer-2: (sumAgg@W2rel + sumX@W2root + cnt*b2) / max(cnt,1)
        float acc = cnt * b2[t];
#pragma unroll 8
        for (int k = 0; k < 64; k++) {
            float A = sAg[0][k] + sAg[1][k] + sAg[2][k] + sAg[3][k];
            float X = sXp[0][k] + sXp[1][k] + sXp[2][k] + sXp[3][k];
            acc += A * W2rel[k * 64 + t] + X * W2root[k * 64 + t];
        }
        sPool[t] = acc / fmaxf(cnt, 1.f);
    }
    __syncthreads();
    if (t < 64) {
        float z = bl1[t];
#pragma unroll 8
        for (int k = 0; k < 64; k++) z = fmaf(sPool[k], Wl1[k * 64 + t], z);
        sz[t] = fmaxf(z, 0.f);
    }
    __syncthreads();
    if (t < 6) {
        float o = bl2[t];
#pragma unroll 8
        for (int k = 0; k < 64; k++) o = fmaf(sz[k], Wl2[k * 6 + t], o);
        out[g * 6 + t] = o;
    }
}

// -------------------- launch --------------------
extern "C" void kernel_launch(void* const* d_in, const int* in_sizes, int n_in,
                              void* d_out, int out_size) {
    const float* x     = (const float*)d_in[0];
    const int*   ei    = (const int*)d_in[1];
    const float* ew    = (const float*)d_in[2];
    const int*   batch = (const int*)d_in[3];
    const float *Wrel0 = (const float*)d_in[4],  *Wroot0 = (const float*)d_in[5],  *b0 = (const float*)d_in[6];
    const float *Wrel1 = (const float*)d_in[7],  *Wroot1 = (const float*)d_in[8],  *b1 = (const float*)d_in[9];
    const float *Wrel2 = (const float*)d_in[10], *Wroot2 = (const float*)d_in[11], *b2 = (const float*)d_in[12];
    const float *g0 = (const float*)d_in[13], *be0 = (const float*)d_in[14];
    const float *g1 = (const float*)d_in[15], *be1 = (const float*)d_in[16];
    const float *Wl1 = (const float*)d_in[17], *bl1 = (const float*)d_in[18];
    const float *Wl2 = (const float*)d_in[19], *bl2 = (const float*)d_in[20];
    float* out = (float*)d_out;

    const int* src = ei;
    const int* dst = ei + EE;

    float *pA, *pB, *pX, *pStats;
    uint4* pH;
    int *pOff, *pCur, *pBsum, *pGoff;
    int2* pEpack;
    cudaGetSymbolAddress((void**)&pA, g_A);
    cudaGetSymbolAddress((void**)&pB, g_B);
    cudaGetSymbolAddress((void**)&pH, g_H);
    cudaGetSymbolAddress((void**)&pX, g_xpad);
    cudaGetSymbolAddress((void**)&pStats, g_stats);
    cudaGetSymbolAddress((void**)&pOff, g_off);
    cudaGetSymbolAddress((void**)&pCur, g_cur);
    cudaGetSymbolAddress((void**)&pBsum, g_bsum);
    cudaGetSymbolAddress((void**)&pGoff, g_goff);
    cudaGetSymbolAddress((void**)&pEpack, g_epack);

    const int smem64 = 64 * 66 * 4 * 2 + 32 * 64 * 8 * 2 + 128 * 4;  // 67072 B
    const int smem9  = (64 * 17 * 2 + 9 * 64 * 2 + 128) * (int)sizeof(float);
    cudaFuncSetAttribute((const void*)node_update64,
                         cudaFuncAttributeMaxDynamicSharedMemorySize, smem64);

    const int NB = (NN + 63) / 64;
    const int SCAN_BLOCKS = (NN + 1 + 1023) / 1024;

    // ---- CSR build + prep ----
    cudaMemsetAsync(pOff, 0, (NN + 1) * sizeof(int));
    prep<<<(EE + 255) / 256, 256>>>(x, pX, dst, pOff, batch, pGoff);
    scan1<<<SCAN_BLOCKS, 1024>>>(pOff, pBsum);
    scan3f<<<SCAN_BLOCKS, 1024>>>(pOff, pBsum, pCur);
    place_kernel<<<(EE + 511) / 512, 512>>>(src, dst, ew, pCur, pEpack);

    // ---- layer 0 ----
    agg_csr4<<<(NN + 63) / 64, 256>>>(pX, pOff, pEpack, pA, pStats);
    node_update9<<<NB, 128, smem9>>>(pA, pX, Wrel0, Wroot0, b0, pB, pStats);
    bn_act_h<<<(NN * 8 + 255) / 256, 256>>>(pB, pStats, g0, be0, pH);

    // ---- layer 1 (separate gather + GEMM, each at best occupancy) ----
    agg_csr_h<<<(NN + 31) / 32, 256>>>(pH, pOff, pEpack, pA);
    node_update64<<<NB, 128, smem64>>>(pA, pH, Wrel1, Wroot1, b1, pB, pStats + 128);
    bn_act_h<<<(NN * 8 + 255) / 256, 256>>>(pB, pStats + 128, g1, be1, pH);

    // ---- layer 2: direct per-graph edge-segment reduction + pooled GEMM + head ----
    pool2_head<<<GG, 256>>>(pH, pOff, pEpack, pGoff, Wrel2, Wroot2, b2,
                            Wl1, bl1, Wl2, bl2, out);
}

// round 8
// speedup vs baseline: 1.2181x; 1.2181x over previous
#include <cuda_runtime.h>
#include <cuda_fp16.h>

#define NN 100000
#define EE 1600000
#define GG 1024

typedef unsigned long long ull;

// -------------------- device scratch --------------------
__device__ float g_A[(size_t)NN * 64];     // aggregation output (fp32)
__device__ float g_B[(size_t)NN * 64];     // raw layer outputs (fp32)
__device__ uint4 g_H[(size_t)NN * 8];      // activated features fp16 (64 halves/node)
__device__ float g_xpad[(size_t)NN * 16];
__device__ int   g_off[NN + 1];
__device__ int   g_cur[NN];
__device__ int   g_bsum[128];
__device__ int2  g_epack[EE];              // (src, weight-bits) grouped by dst
__device__ int   g_goff[GG + 1];
__device__ float g_stats[256];             // [0:128) layer0, [128:256) layer1

__device__ __forceinline__ void fma2(ull& d, ull a, ull b) {
    asm("fma.rn.f32x2 %0, %1, %2, %0;" : "+l"(d) : "l"(a), "l"(b));
}
__device__ __forceinline__ float2 unpack2(ull v) {
    float2 r; asm("mov.b64 {%0,%1}, %2;" : "=f"(r.x), "=f"(r.y) : "l"(v)); return r;
}
__device__ __forceinline__ ull pack2(float lo, float hi) {
    ull r; asm("mov.b64 %0, {%1,%2};" : "=l"(r) : "f"(lo), "f"(hi)); return r;
}

// -------------------- fused prep: hist + xpad + graph bounds --------------------
__global__ void prep(const float* __restrict__ x, float* __restrict__ xp,
                     const int* __restrict__ dst, int* __restrict__ off,
                     const int* __restrict__ batch, int* __restrict__ goff) {
    int i = blockIdx.x * blockDim.x + threadIdx.x;
    if (i < EE) atomicAdd(&off[dst[i] + 1], 1);
    if (i < NN * 16) { int n = i >> 4, c = i & 15; xp[i] = (c < 9) ? x[n * 9 + c] : 0.f; }
    if (i < NN) {
        int bi = batch[i];
        if (i == 0) { for (int g = 0; g <= bi; g++) goff[g] = 0; }
        else { int bp = batch[i - 1]; for (int g = bp + 1; g <= bi; g++) goff[g] = i; }
        if (i == NN - 1) { for (int g = bi + 1; g <= GG; g++) goff[g] = NN; }
    }
}

// -------------------- scan --------------------
__global__ void scan1(int* __restrict__ off, int* __restrict__ bsum) {
    __shared__ int ws[32];
    int g = blockIdx.x * 1024 + threadIdx.x;
    int v = (g <= NN) ? off[g] : 0;
    int lane = threadIdx.x & 31;
#pragma unroll
    for (int d = 1; d < 32; d <<= 1) { int t = __shfl_up_sync(~0u, v, d); if (lane >= d) v += t; }
    if (lane == 31) ws[threadIdx.x >> 5] = v;
    __syncthreads();
    if (threadIdx.x < 32) {
        int t = ws[threadIdx.x];
#pragma unroll
        for (int d = 1; d < 32; d <<= 1) { int u = __shfl_up_sync(~0u, t, d); if (threadIdx.x >= d) t += u; }
        ws[threadIdx.x] = t;
    }
    __syncthreads();
    if (threadIdx.x >= 32) v += ws[(threadIdx.x >> 5) - 1];
    if (g <= NN) off[g] = v;
    if (threadIdx.x == 1023) bsum[blockIdx.x] = v;
}

__global__ void scan3f(int* __restrict__ off, const int* __restrict__ bsum, int* __restrict__ cur) {
    __shared__ int red[32];
    __shared__ int sadd;
    int t = threadIdx.x;
    int v = (t < blockIdx.x) ? bsum[t] : 0;
#pragma unroll
    for (int d = 16; d; d >>= 1) v += __shfl_down_sync(~0u, v, d);
    if ((t & 31) == 0) red[t >> 5] = v;
    __syncthreads();
    if (t == 0) { int r = 0; for (int w = 0; w < 32; w++) r += red[w]; sadd = r; }
    __syncthreads();
    int g = blockIdx.x * 1024 + t;
    if (g > NN) return;
    int val = off[g] + sadd;
    off[g] = val;
    if (g < NN) cur[g] = val;
}

__global__ void place_kernel(const int* __restrict__ src, const int* __restrict__ dst,
                             const float* __restrict__ ew, int* __restrict__ cur,
                             int2* __restrict__ epack) {
    int e = blockIdx.x * blockDim.x + threadIdx.x;
    if (e >= EE) return;
    int p = atomicAdd(&cur[dst[e]], 1);
    epack[p] = make_int2(src[e], __float_as_int(ew[e]));
}

// -------------------- layer-0 CSR aggregation (fp32, unroll-4) ------------------
__global__ void __launch_bounds__(256) agg_csr4(
    const float* __restrict__ h, const int* __restrict__ rowptr,
    const int2* __restrict__ epack, float* __restrict__ agg, float* __restrict__ stats) {
    if (blockIdx.x == 0) stats[threadIdx.x] = 0.f;   // zero both stats banks
    int node = blockIdx.x * 64 + (threadIdx.x >> 2);
    int lane = threadIdx.x & 3;
    if (node >= NN) return;
    int beg = rowptr[node], end = rowptr[node + 1];
    float4 acc = make_float4(0.f, 0.f, 0.f, 0.f);
    int i = beg;
    for (; i + 3 < end; i += 4) {
        int2 e0 = epack[i], e1 = epack[i + 1], e2 = epack[i + 2], e3 = epack[i + 3];
        float4 v0 = ((const float4*)h)[(size_t)e0.x * 4 + lane];
        float4 v1 = ((const float4*)h)[(size_t)e1.x * 4 + lane];
        float4 v2 = ((const float4*)h)[(size_t)e2.x * 4 + lane];
        float4 v3 = ((const float4*)h)[(size_t)e3.x * 4 + lane];
        float w0 = __int_as_float(e0.y), w1 = __int_as_float(e1.y);
        float w2 = __int_as_float(e2.y), w3 = __int_as_float(e3.y);
        acc.x = fmaf(v0.x, w0, acc.x); acc.y = fmaf(v0.y, w0, acc.y);
        acc.z = fmaf(v0.z, w0, acc.z); acc.w = fmaf(v0.w, w0, acc.w);
        acc.x = fmaf(v1.x, w1, acc.x); acc.y = fmaf(v1.y, w1, acc.y);
        acc.z = fmaf(v1.z, w1, acc.z); acc.w = fmaf(v1.w, w1, acc.w);
        acc.x = fmaf(v2.x, w2, acc.x); acc.y = fmaf(v2.y, w2, acc.y);
        acc.z = fmaf(v2.z, w2, acc.z); acc.w = fmaf(v2.w, w2, acc.w);
        acc.x = fmaf(v3.x, w3, acc.x); acc.y = fmaf(v3.y, w3, acc.y);
        acc.z = fmaf(v3.z, w3, acc.z); acc.w = fmaf(v3.w, w3, acc.w);
    }
    for (; i < end; ++i) {
        int2 ep = epack[i];
        float w = __int_as_float(ep.y);
        float4 v = ((const float4*)h)[(size_t)ep.x * 4 + lane];
        acc.x = fmaf(v.x, w, acc.x); acc.y = fmaf(v.y, w, acc.y);
        acc.z = fmaf(v.z, w, acc.z); acc.w = fmaf(v.w, w, acc.w);
    }
    ((float4*)agg)[(size_t)node * 4 + lane] = acc;
}

// -------------------- fp16 CSR aggregation (unroll-4) --------------------
__device__ __forceinline__ void accum8(float* acc, uint4 r, float w) {
    __half2* hp = (__half2*)&r;
#pragma unroll
    for (int j = 0; j < 4; j++) {
        float2 f = __half22float2(hp[j]);
        acc[2 * j]     = fmaf(f.x, w, acc[2 * j]);
        acc[2 * j + 1] = fmaf(f.y, w, acc[2 * j + 1]);
    }
}

__global__ void __launch_bounds__(256) agg_csr_h(
    const uint4* __restrict__ h, const int* __restrict__ rowptr,
    const int2* __restrict__ epack, float* __restrict__ agg) {
    int node = blockIdx.x * 32 + (threadIdx.x >> 3);
    int lane = threadIdx.x & 7;
    if (node >= NN) return;
    int beg = rowptr[node], end = rowptr[node + 1];
    float acc[8];
#pragma unroll
    for (int j = 0; j < 8; j++) acc[j] = 0.f;
    int i = beg;
    for (; i + 3 < end; i += 4) {
        int2 e0 = epack[i], e1 = epack[i + 1], e2 = epack[i + 2], e3 = epack[i + 3];
        uint4 r0 = h[(size_t)e0.x * 8 + lane];
        uint4 r1 = h[(size_t)e1.x * 8 + lane];
        uint4 r2 = h[(size_t)e2.x * 8 + lane];
        uint4 r3 = h[(size_t)e3.x * 8 + lane];
        accum8(acc, r0, __int_as_float(e0.y));
        accum8(acc, r1, __int_as_float(e1.y));
        accum8(acc, r2, __int_as_float(e2.y));
        accum8(acc, r3, __int_as_float(e3.y));
    }
    for (; i < end; ++i) {
        int2 e0 = epack[i];
        uint4 r0 = h[(size_t)e0.x * 8 + lane];
        accum8(acc, r0, __int_as_float(e0.y));
    }
    float* dstp = &agg[(size_t)node * 64 + lane * 8];
    *(float4*)dstp       = make_float4(acc[0], acc[1], acc[2], acc[3]);
    *(float4*)(dstp + 4) = make_float4(acc[4], acc[5], acc[6], acc[7]);
}

// -------------------- layer-0 node update (K=9, scalar) --------------------
__global__ void __launch_bounds__(128) node_update9(
    const float* __restrict__ Ag, const float* __restrict__ Xin,
    const float* __restrict__ Wrel, const float* __restrict__ Wroot,
    const float* __restrict__ bias, float* __restrict__ Out, float* stats) {
    constexpr int K = 9, PAD = 17, C4 = 4;
    extern __shared__ float sm[];
    float* sA   = sm;
    float* sX   = sA + 64 * PAD;
    float* sWr  = sX + 64 * PAD;
    float* sWo  = sWr + K * 64;
    float* sSum = sWo + K * 64;
    float* sSq  = sSum + 64;

    const int tid = threadIdx.x;
    const int base = blockIdx.x * 64;

    for (int i = tid; i < K * 16; i += 128) {
        ((float4*)sWr)[i] = ((const float4*)Wrel)[i];
        ((float4*)sWo)[i] = ((const float4*)Wroot)[i];
    }
    for (int i = tid; i < 64 * C4; i += 128) {
        int r = i / C4, c = i - r * C4;
        int n = base + r;
        float4 va = make_float4(0.f, 0.f, 0.f, 0.f), vx = va;
        if (n < NN) {
            va = *(const float4*)&Ag[(size_t)n * 16 + c * 4];
            vx = *(const float4*)&Xin[(size_t)n * 16 + c * 4];
        }
        int o = r * PAD + c * 4;
        sA[o] = va.x; sA[o + 1] = va.y; sA[o + 2] = va.z; sA[o + 3] = va.w;
        sX[o] = vx.x; sX[o + 1] = vx.y; sX[o + 2] = vx.z; sX[o + 3] = vx.w;
    }
    if (tid < 64) { sSum[tid] = 0.f; sSq[tid] = 0.f; }
    __syncthreads();

    const int fg = (tid & 7) * 8;
    const int ng = (tid >> 3) * 4;

    float acc[4][8];
#pragma unroll
    for (int i = 0; i < 4; i++)
#pragma unroll
        for (int j = 0; j < 8; j++) acc[i][j] = 0.f;

#pragma unroll
    for (int k = 0; k < K; ++k) {
        float a[4], xv[4];
#pragma unroll
        for (int i = 0; i < 4; i++) {
            a[i]  = sA[(ng + i) * PAD + k];
            xv[i] = sX[(ng + i) * PAD + k];
        }
        float wr[8], wo[8];
        *(float4*)&wr[0] = *(const float4*)&sWr[k * 64 + fg];
        *(float4*)&wr[4] = *(const float4*)&sWr[k * 64 + fg + 4];
        *(float4*)&wo[0] = *(const float4*)&sWo[k * 64 + fg];
        *(float4*)&wo[4] = *(const float4*)&sWo[k * 64 + fg + 4];
#pragma unroll
        for (int i = 0; i < 4; i++)
#pragma unroll
            for (int j = 0; j < 8; j++)
                acc[i][j] = fmaf(xv[i], wo[j], fmaf(a[i], wr[j], acc[i][j]));
    }

    float bz[8];
    *(float4*)&bz[0] = *(const float4*)&bias[fg];
    *(float4*)&bz[4] = *(const float4*)&bias[fg + 4];

    float s[8], q[8];
#pragma unroll
    for (int j = 0; j < 8; j++) { s[j] = 0.f; q[j] = 0.f; }

#pragma unroll
    for (int i = 0; i < 4; i++) {
        int n = base + ng + i;
        if (n < NN) {
            float o[8];
#pragma unroll
            for (int j = 0; j < 8; j++) o[j] = acc[i][j] + bz[j];
            *(float4*)&Out[(size_t)n * 64 + fg]     = make_float4(o[0], o[1], o[2], o[3]);
            *(float4*)&Out[(size_t)n * 64 + fg + 4] = make_float4(o[4], o[5], o[6], o[7]);
#pragma unroll
            for (int j = 0; j < 8; j++) { s[j] += o[j]; q[j] += o[j] * o[j]; }
        }
    }
#pragma unroll
    for (int j = 0; j < 8; j++) {
        atomicAdd(&sSum[fg + j], s[j]);
        atomicAdd(&sSq[fg + j], q[j]);
    }
    __syncthreads();
    if (tid < 64) {
        atomicAdd(&stats[tid], sSum[tid]);
        atomicAdd(&stats[64 + tid], sSq[tid]);
    }
}

// -------------------- f32x2 node update (K=64), fp16 Xin --------------------
__global__ void __launch_bounds__(128) node_update64(
    const float* __restrict__ Ag, const uint4* __restrict__ Xh,
    const float* __restrict__ Wrel, const float* __restrict__ Wroot,
    const float* __restrict__ bias, float* __restrict__ Out, float* stats) {
    constexpr int PAD = 66;
    extern __shared__ float sm[];
    float* sA   = sm;
    float* sX   = sA + 64 * PAD;
    ull*   sWr  = (ull*)(sX + 64 * PAD);
    ull*   sWo  = sWr + 32 * 64;
    float* sSum = (float*)(sWo + 32 * 64);
    float* sSq  = sSum + 64;

    const int tid = threadIdx.x;
    const int base = blockIdx.x * 64;

    for (int idx = tid; idx < 32 * 16; idx += 128) {
        int k2 = idx >> 4, c4 = idx & 15;
        float4 r0 = ((const float4*)Wrel)[(2 * k2) * 16 + c4];
        float4 r1 = ((const float4*)Wrel)[(2 * k2 + 1) * 16 + c4];
        ull* p = &sWr[k2 * 64 + c4 * 4];
        p[0] = pack2(r0.x, r1.x); p[1] = pack2(r0.y, r1.y);
        p[2] = pack2(r0.z, r1.z); p[3] = pack2(r0.w, r1.w);
        r0 = ((const float4*)Wroot)[(2 * k2) * 16 + c4];
        r1 = ((const float4*)Wroot)[(2 * k2 + 1) * 16 + c4];
        p = &sWo[k2 * 64 + c4 * 4];
        p[0] = pack2(r0.x, r1.x); p[1] = pack2(r0.y, r1.y);
        p[2] = pack2(r0.z, r1.z); p[3] = pack2(r0.w, r1.w);
    }
    for (int i = tid; i < 64 * 16; i += 128) {
        int r = i >> 4, c = i & 15;
        int n = base + r;
        float4 va = make_float4(0.f, 0.f, 0.f, 0.f);
        if (n < NN) va = *(const float4*)&Ag[(size_t)n * 64 + c * 4];
        int o = r * PAD + c * 4;
        sA[o] = va.x; sA[o + 1] = va.y; sA[o + 2] = va.z; sA[o + 3] = va.w;
    }
    for (int i = tid; i < 64 * 8; i += 128) {
        int r = i >> 3, c = i & 7;
        int n = base + r;
        uint4 v = make_uint4(0u, 0u, 0u, 0u);
        if (n < NN) v = Xh[(size_t)n * 8 + c];
        __half2* hp = (__half2*)&v;
        float* o = &sX[r * PAD + c * 8];
#pragma unroll
        for (int j = 0; j < 4; j++) {
            float2 f = __half22float2(hp[j]);
            o[2 * j] = f.x; o[2 * j + 1] = f.y;
        }
    }
    if (tid < 64) { sSum[tid] = 0.f; sSq[tid] = 0.f; }
    __syncthreads();

    const int f0 = (tid & 7) * 2;
    const int ng = (tid >> 3) * 4;

    ull acc2[4][8];
#pragma unroll
    for (int i = 0; i < 4; i++)
#pragma unroll
        for (int j = 0; j < 8; j++) acc2[i][j] = 0ull;

#pragma unroll 2
    for (int k2 = 0; k2 < 32; ++k2) {
        ull av[4], xv[4];
#pragma unroll
        for (int i = 0; i < 4; i++) {
            av[i] = *(const ull*)&sA[(ng + i) * PAD + 2 * k2];
            xv[i] = *(const ull*)&sX[(ng + i) * PAD + 2 * k2];
        }
#pragma unroll
        for (int c = 0; c < 4; c++) {
            ulonglong2 wr = *(const ulonglong2*)&sWr[k2 * 64 + f0 + 16 * c];
            ulonglong2 wo = *(const ulonglong2*)&sWo[k2 * 64 + f0 + 16 * c];
#pragma unroll
            for (int i = 0; i < 4; i++) {
                fma2(acc2[i][2 * c],     av[i], wr.x);
                fma2(acc2[i][2 * c + 1], av[i], wr.y);
                fma2(acc2[i][2 * c],     xv[i], wo.x);
                fma2(acc2[i][2 * c + 1], xv[i], wo.y);
            }
        }
    }

    float bz[8];
#pragma unroll
    for (int c = 0; c < 4; c++) {
        float2 b2 = *(const float2*)&bias[f0 + 16 * c];
        bz[2 * c] = b2.x; bz[2 * c + 1] = b2.y;
    }

    float s[8], q[8];
#pragma unroll
    for (int j = 0; j < 8; j++) { s[j] = 0.f; q[j] = 0.f; }

#pragma unroll
    for (int i = 0; i < 4; i++) {
        int n = base + ng + i;
        if (n < NN) {
#pragma unroll
            for (int c = 0; c < 4; c++) {
                float2 e0 = unpack2(acc2[i][2 * c]);
                float2 e1 = unpack2(acc2[i][2 * c + 1]);
                float o0 = e0.x + e0.y + bz[2 * c];
                float o1 = e1.x + e1.y + bz[2 * c + 1];
                *(float2*)&Out[(size_t)n * 64 + f0 + 16 * c] = make_float2(o0, o1);
                s[2 * c] += o0; q[2 * c] += o0 * o0;
                s[2 * c + 1] += o1; q[2 * c + 1] += o1 * o1;
            }
        }
    }
#pragma unroll
    for (int c = 0; c < 4; c++) {
        atomicAdd(&sSum[f0 + 16 * c],     s[2 * c]);
        atomicAdd(&sSum[f0 + 16 * c + 1], s[2 * c + 1]);
        atomicAdd(&sSq[f0 + 16 * c],      q[2 * c]);
        atomicAdd(&sSq[f0 + 16 * c + 1],  q[2 * c + 1]);
    }
    __syncthreads();
    if (tid < 64) {
        atomicAdd(&stats[tid], sSum[tid]);
        atomicAdd(&stats[64 + tid], sSq[tid]);
    }
}

// -------------------- BN finalize + apply + ReLU + fp16 convert (fused) --------
__global__ void __launch_bounds__(256) bn_act_h(
    const float* __restrict__ in, const float* __restrict__ stats,
    const float* __restrict__ g, const float* __restrict__ be,
    uint4* __restrict__ outh) {
    __shared__ float sc[64], sh[64];
    if (threadIdx.x < 64) {
        int f = threadIdx.x;
        const float inv = 1.f / (float)NN;
        float m = stats[f] * inv;
        float var = stats[64 + f] * inv - m * m;
        float s = g[f] * rsqrtf(var + 1e-5f);
        sc[f] = s;
        sh[f] = fmaf(-m, s, be[f]);
    }
    __syncthreads();
    int i = blockIdx.x * blockDim.x + threadIdx.x;
    if (i >= NN * 8) return;
    int c8 = (i & 7) * 8;
    float4 a = ((const float4*)in)[2 * i];
    float4 b = ((const float4*)in)[2 * i + 1];
    a.x = fmaxf(fmaf(a.x, sc[c8 + 0], sh[c8 + 0]), 0.f);
    a.y = fmaxf(fmaf(a.y, sc[c8 + 1], sh[c8 + 1]), 0.f);
    a.z = fmaxf(fmaf(a.z, sc[c8 + 2], sh[c8 + 2]), 0.f);
    a.w = fmaxf(fmaf(a.w, sc[c8 + 3], sh[c8 + 3]), 0.f);
    b.x = fmaxf(fmaf(b.x, sc[c8 + 4], sh[c8 + 4]), 0.f);
    b.y = fmaxf(fmaf(b.y, sc[c8 + 5], sh[c8 + 5]), 0.f);
    b.z = fmaxf(fmaf(b.z, sc[c8 + 6], sh[c8 + 6]), 0.f);
    b.w = fmaxf(fmaf(b.w, sc[c8 + 7], sh[c8 + 7]), 0.f);
    __half2 h0 = __floats2half2_rn(a.x, a.y);
    __half2 h1 = __floats2half2_rn(a.z, a.w);
    __half2 h2 = __floats2half2_rn(b.x, b.y);
    __half2 h3 = __floats2half2_rn(b.z, b.w);
    uint4 o;
    o.x = *(unsigned*)&h0; o.y = *(unsigned*)&h1;
    o.z = *(unsigned*)&h2; o.w = *(unsigned*)&h3;
    outh[i] = o;
}

// -------------------- layer-2 pooled GEMM + MLP head (from g_A; R6 variant) ----
__global__ void pool2_head(const float* __restrict__ Ag, const uint4* __restrict__ Xh,
                           const float* __restrict__ W2rel, const float* __restrict__ W2root,
                           const float* __restrict__ b2, const int* __restrict__ goff,
                           const float* __restrict__ Wl1, const float* __restrict__ bl1,
                           const float* __restrict__ Wl2, const float* __restrict__ bl2,
                           float* __restrict__ out) {
    __shared__ float sAg[64], sXp[64], sPool[64], sz[64];
    int g = blockIdx.x, t = threadIdx.x;
    int beg = goff[g], end = goff[g + 1];
    const __half* xh = (const __half*)Xh;
    float sa = 0.f, sx = 0.f;
    for (int n = beg; n < end; ++n) {
        sa += Ag[(size_t)n * 64 + t];
        sx += __half2float(xh[(size_t)n * 64 + t]);
    }
    sAg[t] = sa; sXp[t] = sx;
    __syncthreads();
    float cnt = (float)(end - beg);
    float acc = cnt * b2[t];
#pragma unroll 8
    for (int k = 0; k < 64; k++)
        acc += sAg[k] * W2rel[k * 64 + t] + sXp[k] * W2root[k * 64 + t];
    sPool[t] = acc / fmaxf(cnt, 1.f);
    __syncthreads();
    float z = bl1[t];
#pragma unroll 8
    for (int k = 0; k < 64; k++) z = fmaf(sPool[k], Wl1[k * 64 + t], z);
    sz[t] = fmaxf(z, 0.f);
    __syncthreads();
    if (t < 6) {
        float o = bl2[t];
#pragma unroll 8
        for (int k = 0; k < 64; k++) o = fmaf(sz[k], Wl2[k * 6 + t], o);
        out[g * 6 + t] = o;
    }
}

// -------------------- launch --------------------
extern "C" void kernel_launch(void* const* d_in, const int* in_sizes, int n_in,
                              void* d_out, int out_size) {
    const float* x     = (const float*)d_in[0];
    const int*   ei    = (const int*)d_in[1];
    const float* ew    = (const float*)d_in[2];
    const int*   batch = (const int*)d_in[3];
    const float *Wrel0 = (const float*)d_in[4],  *Wroot0 = (const float*)d_in[5],  *b0 = (const float*)d_in[6];
    const float *Wrel1 = (const float*)d_in[7],  *Wroot1 = (const float*)d_in[8],  *b1 = (const float*)d_in[9];
    const float *Wrel2 = (const float*)d_in[10], *Wroot2 = (const float*)d_in[11], *b2 = (const float*)d_in[12];
    const float *g0 = (const float*)d_in[13], *be0 = (const float*)d_in[14];
    const float *g1 = (const float*)d_in[15], *be1 = (const float*)d_in[16];
    const float *Wl1 = (const float*)d_in[17], *bl1 = (const float*)d_in[18];
    const float *Wl2 = (const float*)d_in[19], *bl2 = (const float*)d_in[20];
    float* out = (float*)d_out;

    const int* src = ei;
    const int* dst = ei + EE;

    float *pA, *pB, *pX, *pStats;
    uint4* pH;
    int *pOff, *pCur, *pBsum, *pGoff;
    int2* pEpack;
    cudaGetSymbolAddress((void**)&pA, g_A);
    cudaGetSymbolAddress((void**)&pB, g_B);
    cudaGetSymbolAddress((void**)&pH, g_H);
    cudaGetSymbolAddress((void**)&pX, g_xpad);
    cudaGetSymbolAddress((void**)&pStats, g_stats);
    cudaGetSymbolAddress((void**)&pOff, g_off);
    cudaGetSymbolAddress((void**)&pCur, g_cur);
    cudaGetSymbolAddress((void**)&pBsum, g_bsum);
    cudaGetSymbolAddress((void**)&pGoff, g_goff);
    cudaGetSymbolAddress((void**)&pEpack, g_epack);

    const int smem64 = 64 * 66 * 4 * 2 + 32 * 64 * 8 * 2 + 128 * 4;  // 67072 B
    const int smem9  = (64 * 17 * 2 + 9 * 64 * 2 + 128) * (int)sizeof(float);
    cudaFuncSetAttribute((const void*)node_update64,
                         cudaFuncAttributeMaxDynamicSharedMemorySize, smem64);

    const int NB = (NN + 63) / 64;
    const int SCAN_BLOCKS = (NN + 1 + 1023) / 1024;

    // ---- CSR build + prep ----
    cudaMemsetAsync(pOff, 0, (NN + 1) * sizeof(int));
    prep<<<(EE + 255) / 256, 256>>>(x, pX, dst, pOff, batch, pGoff);
    scan1<<<SCAN_BLOCKS, 1024>>>(pOff, pBsum);
    scan3f<<<SCAN_BLOCKS, 1024>>>(pOff, pBsum, pCur);
    place_kernel<<<(EE + 511) / 512, 512>>>(src, dst, ew, pCur, pEpack);

    // ---- layer 0 ----
    agg_csr4<<<(NN + 63) / 64, 256>>>(pX, pOff, pEpack, pA, pStats);
    node_update9<<<NB, 128, smem9>>>(pA, pX, Wrel0, Wroot0, b0, pB, pStats);
    bn_act_h<<<(NN * 8 + 255) / 256, 256>>>(pB, pStats, g0, be0, pH);

    // ---- layer 1 (split gather + GEMM, unroll-4 gather) ----
    agg_csr_h<<<(NN + 31) / 32, 256>>>(pH, pOff, pEpack, pA);
    node_update64<<<NB, 128, smem64>>>(pA, pH, Wrel1, Wroot1, b1, pB, pStats + 128);
    bn_act_h<<<(NN * 8 + 255) / 256, 256>>>(pB, pStats + 128, g1, be1, pH);

    // ---- layer 2: gather then pooled GEMM + head (R6 measured-good path) ----
    agg_csr_h<<<(NN + 31) / 32, 256>>>(pH, pOff, pEpack, pA);
    pool2_head<<<GG, 64>>>(pA, pH, Wrel2, Wroot2, b2, pGoff, Wl1, bl1, Wl2, bl2, out);
}